// round 1
// baseline (speedup 1.0000x reference)
#include <cuda_runtime.h>
#include <math.h>

// ---------------------------------------------------------------------------
// Problem constants
// ---------------------------------------------------------------------------
#define MTOK   131072          // B * H * W tokens
#define CDIM   192
#define HIDDEN 768
#define HEADS  6
#define HDIM   32
#define SCALE  0.17677669529663687f   // 32^-0.5

// ---------------------------------------------------------------------------
// Scratch (static device globals; no allocation allowed)
// ---------------------------------------------------------------------------
__device__ float g_xn [131072 * 192];   // LN output (reused for both LNs)
__device__ float g_q  [131072 * 192];   // q projection
__device__ float g_kv [131072 * 96];    // kv projection
__device__ float g_aw [131072 * 192];   // attention output (token layout)
__device__ float g_x1 [131072 * 192];   // post-attention residual
__device__ float g_h1 [131072 * 768];   // ffn1 output (gelu)
__device__ float g_hb [131072 * 768];   // h = h1 + gelu(conv)

// ---------------------------------------------------------------------------
// LayerNorm: one warp per token (C = 192 = 6*32)
// ---------------------------------------------------------------------------
__global__ __launch_bounds__(256)
void ln_kernel(const float* __restrict__ x, const float* __restrict__ g,
               const float* __restrict__ b, float* __restrict__ y)
{
    int warp = blockIdx.x * 8 + (threadIdx.x >> 5);
    int lane = threadIdx.x & 31;
    const float* xr = x + (size_t)warp * CDIM;
    float v[6];
    float s = 0.f, s2 = 0.f;
#pragma unroll
    for (int i = 0; i < 6; i++) {
        v[i] = xr[lane + 32 * i];
        s  += v[i];
        s2 += v[i] * v[i];
    }
#pragma unroll
    for (int o = 16; o; o >>= 1) {
        s  += __shfl_xor_sync(0xffffffffu, s,  o);
        s2 += __shfl_xor_sync(0xffffffffu, s2, o);
    }
    float mu  = s * (1.f / 192.f);
    float var = s2 * (1.f / 192.f) - mu * mu;
    float inv = rsqrtf(var + 1e-5f);
    float* yr = y + (size_t)warp * CDIM;
#pragma unroll
    for (int i = 0; i < 6; i++) {
        int c = lane + 32 * i;
        yr[c] = (v[i] - mu) * inv * g[c] + b[c];
    }
}

// ---------------------------------------------------------------------------
// SGEMM: C[M,N] = A[M,K] @ B[K,N] + bias, with fused epilogues.
// 128x128 block tile, BK=8, 256 threads, 8x8 micro-tile, double-buffered smem.
// EPI: 0 = bias only, 1 = bias + exact gelu, 2 = bias + residual add
// ---------------------------------------------------------------------------
#define BM 128
#define BN 128
#define BKG 8

__device__ __forceinline__ float gelu_exact(float v)
{
    return 0.5f * v * (1.0f + erff(v * 0.70710678118654752f));
}

__device__ __forceinline__ float4 load_b4(const float* __restrict__ B, size_t roff,
                                          int ncol, int N, bool full)
{
    if (full || ncol + 3 < N) {
        return *(const float4*)(B + roff + ncol);
    }
    float4 v;
    v.x = (ncol + 0 < N) ? B[roff + ncol + 0] : 0.f;
    v.y = (ncol + 1 < N) ? B[roff + ncol + 1] : 0.f;
    v.z = (ncol + 2 < N) ? B[roff + ncol + 2] : 0.f;
    v.w = (ncol + 3 < N) ? B[roff + ncol + 3] : 0.f;
    return v;
}

template<int EPI>
__global__ __launch_bounds__(256, 2)
void sgemm_kernel(const float* __restrict__ A, const float* __restrict__ B,
                  const float* __restrict__ bias, const float* __restrict__ res,
                  float* __restrict__ C, int M, int N, int K)
{
    __shared__ float As[2][BKG][BM];
    __shared__ float Bs[2][BKG][BN];

    int tid = threadIdx.x;
    int bm  = blockIdx.y * BM;
    int bn  = blockIdx.x * BN;

    int am  = tid >> 1;            // 0..127
    int ak  = (tid & 1) << 2;      // 0 or 4
    int bk  = tid >> 5;            // 0..7
    int bnn = (tid & 31) << 2;     // 0..124

    const float* Aload = A + (size_t)(bm + am) * K + ak;
    bool bfull = (bn + BN <= N);

    // prologue: tile 0
    float4 aReg = *(const float4*)(Aload);
    float4 bReg = load_b4(B, (size_t)bk * N, bn + bnn, N, bfull);
    As[0][ak + 0][am] = aReg.x;
    As[0][ak + 1][am] = aReg.y;
    As[0][ak + 2][am] = aReg.z;
    As[0][ak + 3][am] = aReg.w;
    *(float4*)&Bs[0][bk][bnn] = bReg;
    __syncthreads();

    int tx = tid & 15, ty = tid >> 4;
    float acc[8][8];
#pragma unroll
    for (int i = 0; i < 8; i++)
#pragma unroll
        for (int j = 0; j < 8; j++) acc[i][j] = 0.f;

    int KT = K / BKG;
    for (int kt = 0; kt < KT; kt++) {
        int cur = kt & 1;
        if (kt + 1 < KT) {
            aReg = *(const float4*)(Aload + (kt + 1) * BKG);
            bReg = load_b4(B, (size_t)((kt + 1) * BKG + bk) * N, bn + bnn, N, bfull);
        }
        float af[8], bf[8];
#pragma unroll
        for (int k = 0; k < BKG; k++) {
            *(float4*)&af[0] = *(const float4*)&As[cur][k][ty * 8];
            *(float4*)&af[4] = *(const float4*)&As[cur][k][ty * 8 + 4];
            *(float4*)&bf[0] = *(const float4*)&Bs[cur][k][tx * 8];
            *(float4*)&bf[4] = *(const float4*)&Bs[cur][k][tx * 8 + 4];
#pragma unroll
            for (int i = 0; i < 8; i++)
#pragma unroll
                for (int j = 0; j < 8; j++)
                    acc[i][j] += af[i] * bf[j];
        }
        if (kt + 1 < KT) {
            int nxt = cur ^ 1;
            As[nxt][ak + 0][am] = aReg.x;
            As[nxt][ak + 1][am] = aReg.y;
            As[nxt][ak + 2][am] = aReg.z;
            As[nxt][ak + 3][am] = aReg.w;
            *(float4*)&Bs[nxt][bk][bnn] = bReg;
            __syncthreads();
        }
    }

    // epilogue
#pragma unroll
    for (int i = 0; i < 8; i++) {
        int m = bm + ty * 8 + i;
        size_t row = (size_t)m * N;
#pragma unroll
        for (int j = 0; j < 8; j += 4) {
            int n = bn + tx * 8 + j;
            if (bfull || n + 3 < N) {
                float4 v;
                v.x = acc[i][j + 0] + bias[n + 0];
                v.y = acc[i][j + 1] + bias[n + 1];
                v.z = acc[i][j + 2] + bias[n + 2];
                v.w = acc[i][j + 3] + bias[n + 3];
                if (EPI == 1) {
                    v.x = gelu_exact(v.x); v.y = gelu_exact(v.y);
                    v.z = gelu_exact(v.z); v.w = gelu_exact(v.w);
                } else if (EPI == 2) {
                    float4 r = *(const float4*)(res + row + n);
                    v.x += r.x; v.y += r.y; v.z += r.z; v.w += r.w;
                }
                *(float4*)(C + row + n) = v;
            } else {
#pragma unroll
                for (int u = 0; u < 4; u++) {
                    int nn = n + u;
                    if (nn < N) {
                        float v = acc[i][j + u] + bias[nn];
                        if (EPI == 1) v = gelu_exact(v);
                        else if (EPI == 2) v += res[row + nn];
                        C[row + nn] = v;
                    }
                }
            }
        }
    }
}

// ---------------------------------------------------------------------------
// Windowed PSA attention. One block per 8x8 window; 384 threads = (head, q).
// kv token (ph,pw) channel e=h*32+d gathers kvproj of window token
// (2ph + e/96, 2pw + (e/48)%2), channel e%48 (k) / 48+e%48 (v).
// Relative-position bias computed analytically, matching _aligned_index.
// ---------------------------------------------------------------------------
__global__ __launch_bounds__(384)
void attn_kernel(const float* __restrict__ q, const float* __restrict__ kvp,
                 const float* __restrict__ bt, float* __restrict__ aw)
{
    __shared__ float k_s[HEADS * 16 * HDIM];   // [h][tok][d]
    __shared__ float v_s[HEADS * 16 * HDIM];

    int w  = blockIdx.x;                  // 0..2047
    int b  = w >> 10;
    int wi = (w >> 5) & 31;
    int wj = w & 31;
    size_t base = (size_t)b * 65536 + (size_t)(wi * 8) * 256 + wj * 8;

    int tid = threadIdx.x;
    for (int f = tid; f < HEADS * 16 * HDIM; f += 384) {
        int h   = f >> 9;
        int tok = (f >> 5) & 15;
        int d   = f & 31;
        int e   = h * HDIM + d;
        int a   = e / 96;
        int bb  = (e / 48) & 1;
        int ch  = e % 48;
        int ii  = ((tok >> 2) << 1) + a;
        int jj  = ((tok & 3) << 1) + bb;
        size_t g = base + (size_t)ii * 256 + jj;
        const float* kvrow = kvp + g * 96;
        k_s[f] = kvrow[ch];
        v_s[f] = kvrow[48 + ch];
    }
    __syncthreads();

    int h  = tid / 64;
    int qi = tid & 63;
    int i  = qi >> 3, j = qi & 7;
    size_t g = base + (size_t)i * 256 + j;

    float qr[32];
    const float4* qp = (const float4*)(q + g * CDIM + h * HDIM);
#pragma unroll
    for (int u = 0; u < 8; u++) {
        float4 t = qp[u];
        qr[4 * u + 0] = t.x * SCALE;
        qr[4 * u + 1] = t.y * SCALE;
        qr[4 * u + 2] = t.z * SCALE;
        qr[4 * u + 3] = t.w * SCALE;
    }

    float s[16];
    float mx = -1e30f;
    const float* kh = k_s + h * 512;
#pragma unroll
    for (int kv = 0; kv < 16; kv++) {
        float acc = 0.f;
#pragma unroll
        for (int d = 0; d < 32; d++) acc += qr[d] * kh[kv * 32 + d];
        int dh = (i >> 1) - (kv >> 2) + 3;
        int dw = (j >> 1) - (kv & 3) + 3;
        acc += bt[(dh * 7 + dw) * HEADS + h];
        s[kv] = acc;
        mx = fmaxf(mx, acc);
    }
    float sum = 0.f;
#pragma unroll
    for (int kv = 0; kv < 16; kv++) { s[kv] = __expf(s[kv] - mx); sum += s[kv]; }
    float inv = 1.f / sum;

    float o[32];
#pragma unroll
    for (int d = 0; d < 32; d++) o[d] = 0.f;
    const float* vh = v_s + h * 512;
#pragma unroll
    for (int kv = 0; kv < 16; kv++) {
        float p = s[kv] * inv;
#pragma unroll
        for (int d = 0; d < 32; d++) o[d] += p * vh[kv * 32 + d];
    }

    float* op = aw + g * CDIM + h * HDIM;
#pragma unroll
    for (int u = 0; u < 8; u++)
        ((float4*)op)[u] = make_float4(o[4 * u], o[4 * u + 1], o[4 * u + 2], o[4 * u + 3]);
}

// ---------------------------------------------------------------------------
// Depthwise 5x5 conv (pad 2) + gelu + residual:  out = h1 + gelu(conv(h1)+b)
// Thread = one channel of one (b,y) row; sweeps x with a 5x5 register ring,
// 5 global loads per output (center tap doubles as the residual read).
// ---------------------------------------------------------------------------
__global__ __launch_bounds__(256)
void dwconv_kernel(const float* __restrict__ h1, const float* __restrict__ wk,
                   const float* __restrict__ wb, float* __restrict__ out)
{
    int c = blockIdx.x * 256 + threadIdx.x;   // 0..767
    int y = blockIdx.y;
    int b = blockIdx.z;

    float w[25];
#pragma unroll
    for (int t = 0; t < 25; t++) w[t] = wk[c * 25 + t];
    float bia = wb[c];

    const float* rowp[5];
    bool rowok[5];
#pragma unroll
    for (int dy = 0; dy < 5; dy++) {
        int yy = y + dy - 2;
        rowok[dy] = ((unsigned)yy < 256u);
        rowp[dy] = h1 + ((size_t)b * 256 + (rowok[dy] ? yy : 0)) * 256 * HIDDEN + c;
    }

    float r[5][5];   // [dy][slot], slot = xx mod 5
#pragma unroll
    for (int dy = 0; dy < 5; dy++) { r[dy][3] = 0.f; r[dy][4] = 0.f; }
#pragma unroll
    for (int pc = 0; pc < 2; pc++)
#pragma unroll
        for (int dy = 0; dy < 5; dy++)
            r[dy][pc] = rowok[dy] ? rowp[dy][(size_t)pc * HIDDEN] : 0.f;

    size_t outbase = ((size_t)b * 256 + y) * 256 * HIDDEN + c;
    for (int x0 = 0; x0 < 260; x0 += 5) {
#pragma unroll
        for (int u = 0; u < 5; u++) {
            int x  = x0 + u;
            int xx = x + 2;
#pragma unroll
            for (int dy = 0; dy < 5; dy++) {
                float v = 0.f;
                if (xx < 256 && rowok[dy]) v = rowp[dy][(size_t)xx * HIDDEN];
                r[dy][(u + 2) % 5] = v;
            }
            if (x < 256) {
                float acc = 0.f;
#pragma unroll
                for (int dy = 0; dy < 5; dy++)
#pragma unroll
                    for (int dx = 0; dx < 5; dx++)
                        acc += r[dy][(u + dx + 3) % 5] * w[dy * 5 + dx];
                float center = r[2][u % 5];
                float gv = acc + bia;
                gv = 0.5f * gv * (1.f + erff(gv * 0.70710678f));
                out[outbase + (size_t)x * HIDDEN] = center + gv;
            }
        }
    }
}

// ---------------------------------------------------------------------------
// Launch
// ---------------------------------------------------------------------------
extern "C" void kernel_launch(void* const* d_in, const int* in_sizes, int n_in,
                              void* d_out, int out_size)
{
    const float* x     = (const float*)d_in[0];
    const float* g1    = (const float*)d_in[1];
    const float* be1   = (const float*)d_in[2];
    const float* wq    = (const float*)d_in[3];
    const float* bq    = (const float*)d_in[4];
    const float* wkv   = (const float*)d_in[5];
    const float* bkv   = (const float*)d_in[6];
    const float* bt    = (const float*)d_in[7];
    const float* wproj = (const float*)d_in[8];
    const float* bproj = (const float*)d_in[9];
    const float* g2    = (const float*)d_in[10];
    const float* be2   = (const float*)d_in[11];
    const float* w1f   = (const float*)d_in[12];
    const float* b1f   = (const float*)d_in[13];
    const float* dwk   = (const float*)d_in[14];
    const float* dwb   = (const float*)d_in[15];
    const float* w2f   = (const float*)d_in[16];
    const float* b2f   = (const float*)d_in[17];
    float* out = (float*)d_out;

    float *xn, *qb, *kvb, *awb, *x1, *h1, *hb;
    cudaGetSymbolAddress((void**)&xn,  g_xn);
    cudaGetSymbolAddress((void**)&qb,  g_q);
    cudaGetSymbolAddress((void**)&kvb, g_kv);
    cudaGetSymbolAddress((void**)&awb, g_aw);
    cudaGetSymbolAddress((void**)&x1,  g_x1);
    cudaGetSymbolAddress((void**)&h1,  g_h1);
    cudaGetSymbolAddress((void**)&hb,  g_hb);

    // 1) LN1
    ln_kernel<<<16384, 256>>>(x, g1, be1, xn);
    // 2) q / kv projections (token layout)
    sgemm_kernel<0><<<dim3(2, 1024), 256>>>(xn, wq,  bq,  nullptr, qb,  MTOK, 192, 192);
    sgemm_kernel<0><<<dim3(1, 1024), 256>>>(xn, wkv, bkv, nullptr, kvb, MTOK, 96,  192);
    // 3) windowed attention (writes output in token layout)
    attn_kernel<<<2048, 384>>>(qb, kvb, bt, awb);
    // 4) proj + residual(x) -> x1
    sgemm_kernel<2><<<dim3(2, 1024), 256>>>(awb, wproj, bproj, x, x1, MTOK, 192, 192);
    // 5) LN2 (reuse xn buffer)
    ln_kernel<<<16384, 256>>>(x1, g2, be2, xn);
    // 6) FFN1 + gelu -> h1
    sgemm_kernel<1><<<dim3(6, 1024), 256>>>(xn, w1f, b1f, nullptr, h1, MTOK, HIDDEN, 192);
    // 7) depthwise conv branch: hb = h1 + gelu(conv5x5(h1) + dwb)
    dwconv_kernel<<<dim3(3, 256, 2), 256>>>(h1, dwk, dwb, hb);
    // 8) FFN2 + residual(x1) -> out
    sgemm_kernel<2><<<dim3(2, 1024), 256>>>(hb, w2f, b2f, x1, out, MTOK, 192, HIDDEN);
}

// round 2
// speedup vs baseline: 1.7514x; 1.7514x over previous
#include <cuda_runtime.h>
#include <math.h>

// ---------------------------------------------------------------------------
// Problem constants
// ---------------------------------------------------------------------------
#define MTOK   131072          // B * H * W tokens
#define CDIM   192
#define HIDDEN 768
#define HEADS  6
#define HDIM   32
#define SCALE  0.17677669529663687f   // 32^-0.5

// ---------------------------------------------------------------------------
// Scratch (static device globals; no allocation allowed)
// ---------------------------------------------------------------------------
__device__ float g_xn [131072 * 192];   // LN output (reused for both LNs)
__device__ float g_q  [131072 * 192];   // q projection
__device__ float g_kv [131072 * 96];    // kv projection
__device__ float g_aw [131072 * 192];   // attention output (token layout)
__device__ float g_x1 [131072 * 192];   // post-attention residual
__device__ float g_h1 [131072 * 768];   // ffn1 output (gelu)
__device__ float g_hb [131072 * 768];   // h = h1 + gelu(conv)

// ---------------------------------------------------------------------------
// LayerNorm: one warp per token (C = 192 = 6*32)
// ---------------------------------------------------------------------------
__global__ __launch_bounds__(256)
void ln_kernel(const float* __restrict__ x, const float* __restrict__ g,
               const float* __restrict__ b, float* __restrict__ y)
{
    int warp = blockIdx.x * 8 + (threadIdx.x >> 5);
    int lane = threadIdx.x & 31;
    const float* xr = x + (size_t)warp * CDIM;
    float v[6];
    float s = 0.f, s2 = 0.f;
#pragma unroll
    for (int i = 0; i < 6; i++) {
        v[i] = xr[lane + 32 * i];
        s  += v[i];
        s2 += v[i] * v[i];
    }
#pragma unroll
    for (int o = 16; o; o >>= 1) {
        s  += __shfl_xor_sync(0xffffffffu, s,  o);
        s2 += __shfl_xor_sync(0xffffffffu, s2, o);
    }
    float mu  = s * (1.f / 192.f);
    float var = s2 * (1.f / 192.f) - mu * mu;
    float inv = rsqrtf(var + 1e-5f);
    float* yr = y + (size_t)warp * CDIM;
#pragma unroll
    for (int i = 0; i < 6; i++) {
        int c = lane + 32 * i;
        yr[c] = (v[i] - mu) * inv * g[c] + b[c];
    }
}

// ---------------------------------------------------------------------------
// TF32 tensor-core GEMM: C[M,N] = A[M,K] @ B[K,N] + bias, fused epilogues.
// Block tile 128x96, BK=32, 256 threads (8 warps as 2m x 4n, warp tile 64x24).
// mma.sync.aligned.m16n8k8.row.col.f32.tf32.tf32.f32
// Smem pads (36 / 104) make all fragment LDS bank-conflict-free.
// EPI: 0 = bias, 1 = bias+gelu, 2 = bias+residual
// M % 128 == 0, N % 96 == 0, K % 32 == 0 are guaranteed by the shapes used.
// ---------------------------------------------------------------------------
#define BM 128
#define BN 96
#define BK 32
#define ASTR 36     // padded row stride of As (floats)
#define BSTR 104    // padded row stride of Bs (floats)
#define ASZ (BM * ASTR)     // 4608 floats per stage
#define BSZ (BK * BSTR)     // 3328 floats per stage
#define GSMEM ((ASZ + BSZ) * 2 * 4)   // 63488 bytes

__device__ __forceinline__ float gelu_exact(float v)
{
    return 0.5f * v * (1.0f + erff(v * 0.70710678118654752f));
}

__device__ __forceinline__ float f2tf32(float f)
{
    unsigned u;
    asm("cvt.rna.tf32.f32 %0, %1;" : "=r"(u) : "f"(f));
    return __uint_as_float(u);
}

template<int EPI>
__global__ __launch_bounds__(256, 2)
void tgemm_kernel(const float* __restrict__ A, const float* __restrict__ B,
                  const float* __restrict__ bias, const float* __restrict__ res,
                  float* __restrict__ C, int M, int N, int K)
{
    extern __shared__ float sm[];
    float* Asm[2] = { sm,            sm + ASZ };
    float* Bsm[2] = { sm + 2 * ASZ,  sm + 2 * ASZ + BSZ };

    int tid = threadIdx.x;
    int bm  = blockIdx.y * BM;
    int bn  = blockIdx.x * BN;

    // ---- global load mappings ----
    // A: thread covers 16 consecutive floats of one row (2 threads per row)
    int ar = tid >> 1;
    int ac = (tid & 1) << 4;
    const float* Aptr = A + (size_t)(bm + ar) * K + ac;
    // B: 3 float4 chunks; idx = tid + 256*i, row = idx/24, col4 = idx%24
    int br[3], bc[3];
#pragma unroll
    for (int i = 0; i < 3; i++) {
        int idx = tid + 256 * i;
        br[i] = idx / 24;
        bc[i] = (idx % 24) << 2;
    }

    float4 areg[4], breg[3];

    // ---- prologue: tile 0 ----
#pragma unroll
    for (int i = 0; i < 4; i++) areg[i] = *(const float4*)(Aptr + i * 4);
#pragma unroll
    for (int i = 0; i < 3; i++)
        breg[i] = *(const float4*)(B + (size_t)br[i] * N + bn + bc[i]);
#pragma unroll
    for (int i = 0; i < 4; i++) {
        float* d = Asm[0] + ar * ASTR + ac + i * 4;
        d[0] = f2tf32(areg[i].x); d[1] = f2tf32(areg[i].y);
        d[2] = f2tf32(areg[i].z); d[3] = f2tf32(areg[i].w);
    }
#pragma unroll
    for (int i = 0; i < 3; i++) {
        float* d = Bsm[0] + br[i] * BSTR + bc[i];
        d[0] = f2tf32(breg[i].x); d[1] = f2tf32(breg[i].y);
        d[2] = f2tf32(breg[i].z); d[3] = f2tf32(breg[i].w);
    }
    __syncthreads();

    // ---- warp / lane mapping ----
    int lane = tid & 31;
    int warp = tid >> 5;
    int wm = (warp & 1) << 6;        // 0 / 64
    int wn = (warp >> 1) * 24;       // 0 / 24 / 48 / 72
    int g  = lane >> 2;              // 0..7
    int tc = lane & 3;               // 0..3

    float acc[4][3][4];
#pragma unroll
    for (int mt = 0; mt < 4; mt++)
#pragma unroll
        for (int nt = 0; nt < 3; nt++)
#pragma unroll
            for (int r = 0; r < 4; r++) acc[mt][nt][r] = 0.f;

    int KT = K / BK;
    for (int kt = 0; kt < KT; kt++) {
        int cur = kt & 1;
        if (kt + 1 < KT) {
            const float* Ap = Aptr + (kt + 1) * BK;
#pragma unroll
            for (int i = 0; i < 4; i++) areg[i] = *(const float4*)(Ap + i * 4);
#pragma unroll
            for (int i = 0; i < 3; i++)
                breg[i] = *(const float4*)(B + (size_t)((kt + 1) * BK + br[i]) * N + bn + bc[i]);
        }

        const float* as = Asm[cur];
        const float* bs = Bsm[cur];
#pragma unroll
        for (int ks = 0; ks < 4; ks++) {
            int k0 = ks << 3;
            unsigned af[4][4], bf[3][2];
#pragma unroll
            for (int mt = 0; mt < 4; mt++) {
                const float* p = as + (wm + mt * 16 + g) * ASTR + k0 + tc;
                af[mt][0] = __float_as_uint(p[0]);
                af[mt][1] = __float_as_uint(p[8 * ASTR]);
                af[mt][2] = __float_as_uint(p[4]);
                af[mt][3] = __float_as_uint(p[8 * ASTR + 4]);
            }
#pragma unroll
            for (int nt = 0; nt < 3; nt++) {
                const float* p = bs + (k0 + tc) * BSTR + wn + nt * 8 + g;
                bf[nt][0] = __float_as_uint(p[0]);
                bf[nt][1] = __float_as_uint(p[4 * BSTR]);
            }
#pragma unroll
            for (int mt = 0; mt < 4; mt++)
#pragma unroll
                for (int nt = 0; nt < 3; nt++)
                    asm volatile(
                        "mma.sync.aligned.m16n8k8.row.col.f32.tf32.tf32.f32 "
                        "{%0,%1,%2,%3}, {%4,%5,%6,%7}, {%8,%9}, {%0,%1,%2,%3};\n"
                        : "+f"(acc[mt][nt][0]), "+f"(acc[mt][nt][1]),
                          "+f"(acc[mt][nt][2]), "+f"(acc[mt][nt][3])
                        : "r"(af[mt][0]), "r"(af[mt][1]),
                          "r"(af[mt][2]), "r"(af[mt][3]),
                          "r"(bf[nt][0]), "r"(bf[nt][1]));
        }

        if (kt + 1 < KT) {
            int nxt = cur ^ 1;
#pragma unroll
            for (int i = 0; i < 4; i++) {
                float* d = Asm[nxt] + ar * ASTR + ac + i * 4;
                d[0] = f2tf32(areg[i].x); d[1] = f2tf32(areg[i].y);
                d[2] = f2tf32(areg[i].z); d[3] = f2tf32(areg[i].w);
            }
#pragma unroll
            for (int i = 0; i < 3; i++) {
                float* d = Bsm[nxt] + br[i] * BSTR + bc[i];
                d[0] = f2tf32(breg[i].x); d[1] = f2tf32(breg[i].y);
                d[2] = f2tf32(breg[i].z); d[3] = f2tf32(breg[i].w);
            }
            __syncthreads();
        }
    }

    // ---- epilogue: c0,c1 -> row g; c2,c3 -> row g+8; cols 2*tc, 2*tc+1 ----
#pragma unroll
    for (int mt = 0; mt < 4; mt++) {
#pragma unroll
        for (int half = 0; half < 2; half++) {
            int m = bm + wm + mt * 16 + half * 8 + g;
            size_t row = (size_t)m * N;
#pragma unroll
            for (int nt = 0; nt < 3; nt++) {
                int n = bn + wn + nt * 8 + 2 * tc;
                float2 v;
                v.x = acc[mt][nt][half * 2 + 0] + bias[n + 0];
                v.y = acc[mt][nt][half * 2 + 1] + bias[n + 1];
                if (EPI == 1) {
                    v.x = gelu_exact(v.x);
                    v.y = gelu_exact(v.y);
                } else if (EPI == 2) {
                    float2 r = *(const float2*)(res + row + n);
                    v.x += r.x; v.y += r.y;
                }
                *(float2*)(C + row + n) = v;
            }
        }
    }
}

// ---------------------------------------------------------------------------
// Windowed PSA attention. One block per 8x8 window; 384 threads = (head, q).
// ---------------------------------------------------------------------------
__global__ __launch_bounds__(384)
void attn_kernel(const float* __restrict__ q, const float* __restrict__ kvp,
                 const float* __restrict__ bt, float* __restrict__ aw)
{
    __shared__ float k_s[HEADS * 16 * HDIM];   // [h][tok][d]
    __shared__ float v_s[HEADS * 16 * HDIM];

    int w  = blockIdx.x;                  // 0..2047
    int b  = w >> 10;
    int wi = (w >> 5) & 31;
    int wj = w & 31;
    size_t base = (size_t)b * 65536 + (size_t)(wi * 8) * 256 + wj * 8;

    int tid = threadIdx.x;
    for (int f = tid; f < HEADS * 16 * HDIM; f += 384) {
        int h   = f >> 9;
        int tok = (f >> 5) & 15;
        int d   = f & 31;
        int e   = h * HDIM + d;
        int a   = e / 96;
        int bb  = (e / 48) & 1;
        int ch  = e % 48;
        int ii  = ((tok >> 2) << 1) + a;
        int jj  = ((tok & 3) << 1) + bb;
        size_t g = base + (size_t)ii * 256 + jj;
        const float* kvrow = kvp + g * 96;
        k_s[f] = kvrow[ch];
        v_s[f] = kvrow[48 + ch];
    }
    __syncthreads();

    int h  = tid / 64;
    int qi = tid & 63;
    int i  = qi >> 3, j = qi & 7;
    size_t g = base + (size_t)i * 256 + j;

    float qr[32];
    const float4* qp = (const float4*)(q + g * CDIM + h * HDIM);
#pragma unroll
    for (int u = 0; u < 8; u++) {
        float4 t = qp[u];
        qr[4 * u + 0] = t.x * SCALE;
        qr[4 * u + 1] = t.y * SCALE;
        qr[4 * u + 2] = t.z * SCALE;
        qr[4 * u + 3] = t.w * SCALE;
    }

    float s[16];
    float mx = -1e30f;
    const float* kh = k_s + h * 512;
#pragma unroll
    for (int kv = 0; kv < 16; kv++) {
        float acc = 0.f;
#pragma unroll
        for (int d = 0; d < 32; d++) acc += qr[d] * kh[kv * 32 + d];
        int dh = (i >> 1) - (kv >> 2) + 3;
        int dw = (j >> 1) - (kv & 3) + 3;
        acc += bt[(dh * 7 + dw) * HEADS + h];
        s[kv] = acc;
        mx = fmaxf(mx, acc);
    }
    float sum = 0.f;
#pragma unroll
    for (int kv = 0; kv < 16; kv++) { s[kv] = __expf(s[kv] - mx); sum += s[kv]; }
    float inv = 1.f / sum;

    float o[32];
#pragma unroll
    for (int d = 0; d < 32; d++) o[d] = 0.f;
    const float* vh = v_s + h * 512;
#pragma unroll
    for (int kv = 0; kv < 16; kv++) {
        float p = s[kv] * inv;
#pragma unroll
        for (int d = 0; d < 32; d++) o[d] += p * vh[kv * 32 + d];
    }

    float* op = aw + g * CDIM + h * HDIM;
#pragma unroll
    for (int u = 0; u < 8; u++)
        ((float4*)op)[u] = make_float4(o[4 * u], o[4 * u + 1], o[4 * u + 2], o[4 * u + 3]);
}

// ---------------------------------------------------------------------------
// Depthwise 5x5 conv (pad 2) + gelu + residual:  out = h1 + gelu(conv(h1)+b)
// ---------------------------------------------------------------------------
__global__ __launch_bounds__(256)
void dwconv_kernel(const float* __restrict__ h1, const float* __restrict__ wk,
                   const float* __restrict__ wb, float* __restrict__ out)
{
    int c = blockIdx.x * 256 + threadIdx.x;   // 0..767
    int y = blockIdx.y;
    int b = blockIdx.z;

    float w[25];
#pragma unroll
    for (int t = 0; t < 25; t++) w[t] = wk[c * 25 + t];
    float bia = wb[c];

    const float* rowp[5];
    bool rowok[5];
#pragma unroll
    for (int dy = 0; dy < 5; dy++) {
        int yy = y + dy - 2;
        rowok[dy] = ((unsigned)yy < 256u);
        rowp[dy] = h1 + ((size_t)b * 256 + (rowok[dy] ? yy : 0)) * 256 * HIDDEN + c;
    }

    float r[5][5];   // [dy][slot], slot = xx mod 5
#pragma unroll
    for (int dy = 0; dy < 5; dy++) { r[dy][3] = 0.f; r[dy][4] = 0.f; }
#pragma unroll
    for (int pc = 0; pc < 2; pc++)
#pragma unroll
        for (int dy = 0; dy < 5; dy++)
            r[dy][pc] = rowok[dy] ? rowp[dy][(size_t)pc * HIDDEN] : 0.f;

    size_t outbase = ((size_t)b * 256 + y) * 256 * HIDDEN + c;
    for (int x0 = 0; x0 < 260; x0 += 5) {
#pragma unroll
        for (int u = 0; u < 5; u++) {
            int x  = x0 + u;
            int xx = x + 2;
#pragma unroll
            for (int dy = 0; dy < 5; dy++) {
                float v = 0.f;
                if (xx < 256 && rowok[dy]) v = rowp[dy][(size_t)xx * HIDDEN];
                r[dy][(u + 2) % 5] = v;
            }
            if (x < 256) {
                float acc = 0.f;
#pragma unroll
                for (int dy = 0; dy < 5; dy++)
#pragma unroll
                    for (int dx = 0; dx < 5; dx++)
                        acc += r[dy][(u + dx + 3) % 5] * w[dy * 5 + dx];
                float center = r[2][u % 5];
                float gv = acc + bia;
                gv = 0.5f * gv * (1.f + erff(gv * 0.70710678f));
                out[outbase + (size_t)x * HIDDEN] = center + gv;
            }
        }
    }
}

// ---------------------------------------------------------------------------
// Launch
// ---------------------------------------------------------------------------
extern "C" void kernel_launch(void* const* d_in, const int* in_sizes, int n_in,
                              void* d_out, int out_size)
{
    const float* x     = (const float*)d_in[0];
    const float* g1    = (const float*)d_in[1];
    const float* be1   = (const float*)d_in[2];
    const float* wq    = (const float*)d_in[3];
    const float* bq    = (const float*)d_in[4];
    const float* wkv   = (const float*)d_in[5];
    const float* bkv   = (const float*)d_in[6];
    const float* bt    = (const float*)d_in[7];
    const float* wproj = (const float*)d_in[8];
    const float* bproj = (const float*)d_in[9];
    const float* g2    = (const float*)d_in[10];
    const float* be2   = (const float*)d_in[11];
    const float* w1f   = (const float*)d_in[12];
    const float* b1f   = (const float*)d_in[13];
    const float* dwk   = (const float*)d_in[14];
    const float* dwb   = (const float*)d_in[15];
    const float* w2f   = (const float*)d_in[16];
    const float* b2f   = (const float*)d_in[17];
    float* out = (float*)d_out;

    float *xn, *qb, *kvb, *awb, *x1, *h1, *hb;
    cudaGetSymbolAddress((void**)&xn,  g_xn);
    cudaGetSymbolAddress((void**)&qb,  g_q);
    cudaGetSymbolAddress((void**)&kvb, g_kv);
    cudaGetSymbolAddress((void**)&awb, g_aw);
    cudaGetSymbolAddress((void**)&x1,  g_x1);
    cudaGetSymbolAddress((void**)&h1,  g_h1);
    cudaGetSymbolAddress((void**)&hb,  g_hb);

    cudaFuncSetAttribute(tgemm_kernel<0>, cudaFuncAttributeMaxDynamicSharedMemorySize, GSMEM);
    cudaFuncSetAttribute(tgemm_kernel<1>, cudaFuncAttributeMaxDynamicSharedMemorySize, GSMEM);
    cudaFuncSetAttribute(tgemm_kernel<2>, cudaFuncAttributeMaxDynamicSharedMemorySize, GSMEM);

    // 1) LN1
    ln_kernel<<<16384, 256>>>(x, g1, be1, xn);
    // 2) q / kv projections (token layout)
    tgemm_kernel<0><<<dim3(2, 1024), 256, GSMEM>>>(xn, wq,  bq,  nullptr, qb,  MTOK, 192, 192);
    tgemm_kernel<0><<<dim3(1, 1024), 256, GSMEM>>>(xn, wkv, bkv, nullptr, kvb, MTOK, 96,  192);
    // 3) windowed attention (token layout in & out)
    attn_kernel<<<2048, 384>>>(qb, kvb, bt, awb);
    // 4) proj + residual(x) -> x1
    tgemm_kernel<2><<<dim3(2, 1024), 256, GSMEM>>>(awb, wproj, bproj, x, x1, MTOK, 192, 192);
    // 5) LN2 (reuse xn buffer)
    ln_kernel<<<16384, 256>>>(x1, g2, be2, xn);
    // 6) FFN1 + gelu -> h1
    tgemm_kernel<1><<<dim3(8, 1024), 256, GSMEM>>>(xn, w1f, b1f, nullptr, h1, MTOK, HIDDEN, 192);
    // 7) depthwise conv branch: hb = h1 + gelu(conv5x5(h1) + dwb)
    dwconv_kernel<<<dim3(3, 256, 2), 256>>>(h1, dwk, dwb, hb);
    // 8) FFN2 + residual(x1) -> out
    tgemm_kernel<2><<<dim3(2, 1024), 256, GSMEM>>>(hb, w2f, b2f, x1, out, MTOK, 192, HIDDEN);
}

// round 4
// speedup vs baseline: 2.5707x; 1.4678x over previous
#include <cuda_runtime.h>
#include <cuda_bf16.h>
#include <math.h>
#include <stdint.h>

// ---------------------------------------------------------------------------
// Problem constants
// ---------------------------------------------------------------------------
#define MTOK   131072          // B * H * W tokens
#define CDIM   192
#define HIDDEN 768
#define HEADS  6
#define HDIM   32
#define SCALE  0.17677669529663687f   // 32^-0.5

// ---------------------------------------------------------------------------
// Scratch (static device globals; no allocation allowed)
// ---------------------------------------------------------------------------
__device__ float g_xn [131072 * 192];
__device__ float g_q  [131072 * 192];
__device__ float g_kv [131072 * 96];
__device__ float g_aw [131072 * 192];
__device__ float g_x1 [131072 * 192];
__device__ float g_h1 [131072 * 768];
__device__ float g_hb [131072 * 768];

// ---------------------------------------------------------------------------
// Helpers
// ---------------------------------------------------------------------------
__device__ __forceinline__ uint32_t smem_u32(const void* p) {
    uint32_t a;
    asm("{ .reg .u64 t; cvta.to.shared.u64 t, %1; cvt.u32.u64 %0, t; }" : "=r"(a) : "l"(p));
    return a;
}
__device__ __forceinline__ float gelu_exact(float v)
{
    return 0.5f * v * (1.0f + erff(v * 0.70710678118654752f));
}
__device__ __forceinline__ uint32_t pack_bf2(float x, float y)
{
    __nv_bfloat162 p = __floats2bfloat162_rn(x, y);
    return *reinterpret_cast<uint32_t*>(&p);
}

// ---------------------------------------------------------------------------
// LayerNorm: one warp per token (C = 192 = 6*32)
// ---------------------------------------------------------------------------
__global__ __launch_bounds__(256)
void ln_kernel(const float* __restrict__ x, const float* __restrict__ g,
               const float* __restrict__ b, float* __restrict__ y)
{
    int warp = blockIdx.x * 8 + (threadIdx.x >> 5);
    int lane = threadIdx.x & 31;
    const float* xr = x + (size_t)warp * CDIM;
    float v[6];
    float s = 0.f, s2 = 0.f;
#pragma unroll
    for (int i = 0; i < 6; i++) {
        v[i] = xr[lane + 32 * i];
        s  += v[i];
        s2 += v[i] * v[i];
    }
#pragma unroll
    for (int o = 16; o; o >>= 1) {
        s  += __shfl_xor_sync(0xffffffffu, s,  o);
        s2 += __shfl_xor_sync(0xffffffffu, s2, o);
    }
    float mu  = s * (1.f / 192.f);
    float var = s2 * (1.f / 192.f) - mu * mu;
    float inv = rsqrtf(var + 1e-5f);
    float* yr = y + (size_t)warp * CDIM;
#pragma unroll
    for (int i = 0; i < 6; i++) {
        int c = lane + 32 * i;
        yr[c] = (v[i] - mu) * inv * g[c] + b[c];
    }
}

// ---------------------------------------------------------------------------
// BF16 tensor-core GEMM: C[M,N] = A[M,K] @ B[K,N] + bias, fused epilogues.
// Block tile 128x96, BK=32, 256 threads (8 warps = 2m x 4n, warp tile 64x24).
// mma.sync.aligned.m16n8k16.row.col.f32.bf16.bf16.f32, fragments loaded with
// ldmatrix (A: x4 from [m][k]; B: x4/x2 .trans from [k][n] — no STS transpose).
// Padded smem strides (40 / 104 elems) give conflict-free ldmatrix phases.
// EPI: 0 = bias, 1 = bias+gelu, 2 = bias+residual
// Requires M%128==0, N%96==0, K%32==0 (true for all shapes used).
// ---------------------------------------------------------------------------
#define BM 128
#define BN 96
#define BK 32

template<int EPI>
__global__ __launch_bounds__(256, 2)
void bgemm_kernel(const float* __restrict__ A, const float* __restrict__ B,
                  const float* __restrict__ bias, const float* __restrict__ res,
                  float* __restrict__ C, int N, int K)
{
    __shared__ __nv_bfloat16 As[2][BM][40];    // 20480 B
    __shared__ __nv_bfloat16 Bs[2][BK][104];   // 13312 B

    const int tid  = threadIdx.x;
    const int lane = tid & 31;
    const int warp = tid >> 5;
    const int bm   = blockIdx.y * BM;
    const int bn   = blockIdx.x * BN;
    const int KT   = K / BK;

    // ---- global load mappings ----
    const int ar  = tid >> 3;        // A row base (0..31), rows ar + 32*i
    const int ac4 = tid & 7;         // float4 index within 32-float k-slice
    int br[3], bc[3];                // B: 3 float4 per thread
#pragma unroll
    for (int i = 0; i < 3; i++) {
        int idx = tid + 256 * i;
        br[i] = idx / 24;            // k row 0..31
        bc[i] = (idx % 24) << 2;     // n col 0..92
    }

    float4 aReg[4], bReg[3];

    auto fetch = [&](int kt) {
#pragma unroll
        for (int i = 0; i < 4; i++)
            aReg[i] = *(const float4*)(A + (size_t)(bm + ar + 32 * i) * K + kt * BK + ac4 * 4);
#pragma unroll
        for (int i = 0; i < 3; i++)
            bReg[i] = *(const float4*)(B + (size_t)(kt * BK + br[i]) * N + bn + bc[i]);
    };
    auto stage = [&](int buf) {
#pragma unroll
        for (int i = 0; i < 4; i++) {
            uint2 u = make_uint2(pack_bf2(aReg[i].x, aReg[i].y),
                                 pack_bf2(aReg[i].z, aReg[i].w));
            *(uint2*)&As[buf][ar + 32 * i][ac4 * 4] = u;
        }
#pragma unroll
        for (int i = 0; i < 3; i++) {
            uint2 u = make_uint2(pack_bf2(bReg[i].x, bReg[i].y),
                                 pack_bf2(bReg[i].z, bReg[i].w));
            *(uint2*)&Bs[buf][br[i]][bc[i]] = u;
        }
    };

    // ---- prologue ----
    fetch(0);
    stage(0);
    __syncthreads();

    // ---- warp / lane mapping ----
    const int wm = (warp & 1) << 6;          // 0 / 64
    const int wn = (warp >> 1) * 24;         // 0 / 24 / 48 / 72
    const int g  = lane >> 2;                // 0..7
    const int tc = lane & 3;                 // 0..3

    // ldmatrix lane-address components
    const int a_mrow = lane & 15;            // row within m16 tile
    const int a_koff = (lane >> 4) << 3;     // 0 / 8 k offset
    const int b_krow = lane & 15;            // row within k16
    const int b_noff = (lane & 16) ? 8 : 0;  // n offset for x4

    float acc[4][3][4];
#pragma unroll
    for (int mt = 0; mt < 4; mt++)
#pragma unroll
        for (int nt = 0; nt < 3; nt++)
#pragma unroll
            for (int r = 0; r < 4; r++) acc[mt][nt][r] = 0.f;

    for (int kt = 0; kt < KT; kt++) {
        int cur = kt & 1;
        if (kt + 1 < KT) fetch(kt + 1);

#pragma unroll
        for (int ks = 0; ks < 2; ks++) {
            int k0 = ks << 4;
            uint32_t af[4][4];
#pragma unroll
            for (int mt = 0; mt < 4; mt++) {
                uint32_t addr = smem_u32(&As[cur][wm + mt * 16 + a_mrow][k0 + a_koff]);
                asm volatile("ldmatrix.sync.aligned.m8n8.x4.shared.b16 {%0,%1,%2,%3}, [%4];"
                             : "=r"(af[mt][0]), "=r"(af[mt][1]),
                               "=r"(af[mt][2]), "=r"(af[mt][3]) : "r"(addr));
            }
            uint32_t bf[3][2];
            {
                uint32_t addr = smem_u32(&Bs[cur][k0 + b_krow][wn + b_noff]);
                asm volatile("ldmatrix.sync.aligned.m8n8.x4.trans.shared.b16 {%0,%1,%2,%3}, [%4];"
                             : "=r"(bf[0][0]), "=r"(bf[0][1]),
                               "=r"(bf[1][0]), "=r"(bf[1][1]) : "r"(addr));
                uint32_t addr2 = smem_u32(&Bs[cur][k0 + b_krow][wn + 16]);
                asm volatile("ldmatrix.sync.aligned.m8n8.x2.trans.shared.b16 {%0,%1}, [%2];"
                             : "=r"(bf[2][0]), "=r"(bf[2][1]) : "r"(addr2));
            }
#pragma unroll
            for (int mt = 0; mt < 4; mt++)
#pragma unroll
                for (int nt = 0; nt < 3; nt++)
                    asm volatile(
                        "mma.sync.aligned.m16n8k16.row.col.f32.bf16.bf16.f32 "
                        "{%0,%1,%2,%3}, {%4,%5,%6,%7}, {%8,%9}, {%0,%1,%2,%3};\n"
                        : "+f"(acc[mt][nt][0]), "+f"(acc[mt][nt][1]),
                          "+f"(acc[mt][nt][2]), "+f"(acc[mt][nt][3])
                        : "r"(af[mt][0]), "r"(af[mt][1]),
                          "r"(af[mt][2]), "r"(af[mt][3]),
                          "r"(bf[nt][0]), "r"(bf[nt][1]));
        }

        if (kt + 1 < KT) {
            __syncthreads();          // all warps done reading buf cur^1's prior data
            stage(cur ^ 1);
            __syncthreads();
        }
    }

    // ---- epilogue: c0,c1 -> row g; c2,c3 -> row g+8; cols 2*tc, 2*tc+1 ----
#pragma unroll
    for (int mt = 0; mt < 4; mt++) {
#pragma unroll
        for (int half = 0; half < 2; half++) {
            int m = bm + wm + mt * 16 + half * 8 + g;
            size_t row = (size_t)m * N;
#pragma unroll
            for (int nt = 0; nt < 3; nt++) {
                int n = bn + wn + nt * 8 + 2 * tc;
                float2 v;
                v.x = acc[mt][nt][half * 2 + 0] + bias[n + 0];
                v.y = acc[mt][nt][half * 2 + 1] + bias[n + 1];
                if (EPI == 1) {
                    v.x = gelu_exact(v.x);
                    v.y = gelu_exact(v.y);
                } else if (EPI == 2) {
                    float2 r = *(const float2*)(res + row + n);
                    v.x += r.x; v.y += r.y;
                }
                *(float2*)(C + row + n) = v;
            }
        }
    }
}

// ---------------------------------------------------------------------------
// Windowed PSA attention. One block per 8x8 window; 384 threads = (head, q).
// ---------------------------------------------------------------------------
__global__ __launch_bounds__(384)
void attn_kernel(const float* __restrict__ q, const float* __restrict__ kvp,
                 const float* __restrict__ bt, float* __restrict__ aw)
{
    __shared__ float k_s[HEADS * 16 * HDIM];
    __shared__ float v_s[HEADS * 16 * HDIM];

    int w  = blockIdx.x;
    int b  = w >> 10;
    int wi = (w >> 5) & 31;
    int wj = w & 31;
    size_t base = (size_t)b * 65536 + (size_t)(wi * 8) * 256 + wj * 8;

    int tid = threadIdx.x;
    for (int f = tid; f < HEADS * 16 * HDIM; f += 384) {
        int h   = f >> 9;
        int tok = (f >> 5) & 15;
        int d   = f & 31;
        int e   = h * HDIM + d;
        int a   = e / 96;
        int bb  = (e / 48) & 1;
        int ch  = e % 48;
        int ii  = ((tok >> 2) << 1) + a;
        int jj  = ((tok & 3) << 1) + bb;
        size_t g = base + (size_t)ii * 256 + jj;
        const float* kvrow = kvp + g * 96;
        k_s[f] = kvrow[ch];
        v_s[f] = kvrow[48 + ch];
    }
    __syncthreads();

    int h  = tid / 64;
    int qi = tid & 63;
    int i  = qi >> 3, j = qi & 7;
    size_t g = base + (size_t)i * 256 + j;

    float qr[32];
    const float4* qp = (const float4*)(q + g * CDIM + h * HDIM);
#pragma unroll
    for (int u = 0; u < 8; u++) {
        float4 t = qp[u];
        qr[4 * u + 0] = t.x * SCALE;
        qr[4 * u + 1] = t.y * SCALE;
        qr[4 * u + 2] = t.z * SCALE;
        qr[4 * u + 3] = t.w * SCALE;
    }

    float s[16];
    float mx = -1e30f;
    const float* kh = k_s + h * 512;
#pragma unroll
    for (int kv = 0; kv < 16; kv++) {
        float acc = 0.f;
#pragma unroll
        for (int d = 0; d < 32; d++) acc += qr[d] * kh[kv * 32 + d];
        int dh = (i >> 1) - (kv >> 2) + 3;
        int dw = (j >> 1) - (kv & 3) + 3;
        acc += bt[(dh * 7 + dw) * HEADS + h];
        s[kv] = acc;
        mx = fmaxf(mx, acc);
    }
    float sum = 0.f;
#pragma unroll
    for (int kv = 0; kv < 16; kv++) { s[kv] = __expf(s[kv] - mx); sum += s[kv]; }
    float inv = 1.f / sum;

    float o[32];
#pragma unroll
    for (int d = 0; d < 32; d++) o[d] = 0.f;
    const float* vh = v_s + h * 512;
#pragma unroll
    for (int kv = 0; kv < 16; kv++) {
        float p = s[kv] * inv;
#pragma unroll
        for (int d = 0; d < 32; d++) o[d] += p * vh[kv * 32 + d];
    }

    float* op = aw + g * CDIM + h * HDIM;
#pragma unroll
    for (int u = 0; u < 8; u++)
        ((float4*)op)[u] = make_float4(o[4 * u], o[4 * u + 1], o[4 * u + 2], o[4 * u + 3]);
}

// ---------------------------------------------------------------------------
// Depthwise 5x5 conv (pad 2) + gelu + residual:  out = h1 + gelu(conv(h1)+b)
// ---------------------------------------------------------------------------
__global__ __launch_bounds__(256)
void dwconv_kernel(const float* __restrict__ h1, const float* __restrict__ wk,
                   const float* __restrict__ wb, float* __restrict__ out)
{
    int c = blockIdx.x * 256 + threadIdx.x;
    int y = blockIdx.y;
    int b = blockIdx.z;

    float w[25];
#pragma unroll
    for (int t = 0; t < 25; t++) w[t] = wk[c * 25 + t];
    float bia = wb[c];

    const float* rowp[5];
    bool rowok[5];
#pragma unroll
    for (int dy = 0; dy < 5; dy++) {
        int yy = y + dy - 2;
        rowok[dy] = ((unsigned)yy < 256u);
        rowp[dy] = h1 + ((size_t)b * 256 + (rowok[dy] ? yy : 0)) * 256 * HIDDEN + c;
    }

    float r[5][5];
#pragma unroll
    for (int dy = 0; dy < 5; dy++) { r[dy][3] = 0.f; r[dy][4] = 0.f; }
#pragma unroll
    for (int pc = 0; pc < 2; pc++)
#pragma unroll
        for (int dy = 0; dy < 5; dy++)
            r[dy][pc] = rowok[dy] ? rowp[dy][(size_t)pc * HIDDEN] : 0.f;

    size_t outbase = ((size_t)b * 256 + y) * 256 * HIDDEN + c;
    for (int x0 = 0; x0 < 260; x0 += 5) {
#pragma unroll
        for (int u = 0; u < 5; u++) {
            int x  = x0 + u;
            int xx = x + 2;
#pragma unroll
            for (int dy = 0; dy < 5; dy++) {
                float v = 0.f;
                if (xx < 256 && rowok[dy]) v = rowp[dy][(size_t)xx * HIDDEN];
                r[dy][(u + 2) % 5] = v;
            }
            if (x < 256) {
                float acc = 0.f;
#pragma unroll
                for (int dy = 0; dy < 5; dy++)
#pragma unroll
                    for (int dx = 0; dx < 5; dx++)
                        acc += r[dy][(u + dx + 3) % 5] * w[dy * 5 + dx];
                float center = r[2][u % 5];
                float gv = acc + bia;
                gv = 0.5f * gv * (1.f + erff(gv * 0.70710678f));
                out[outbase + (size_t)x * HIDDEN] = center + gv;
            }
        }
    }
}

// ---------------------------------------------------------------------------
// Launch
// ---------------------------------------------------------------------------
extern "C" void kernel_launch(void* const* d_in, const int* in_sizes, int n_in,
                              void* d_out, int out_size)
{
    const float* x     = (const float*)d_in[0];
    const float* g1    = (const float*)d_in[1];
    const float* be1   = (const float*)d_in[2];
    const float* wq    = (const float*)d_in[3];
    const float* bq    = (const float*)d_in[4];
    const float* wkv   = (const float*)d_in[5];
    const float* bkv   = (const float*)d_in[6];
    const float* bt    = (const float*)d_in[7];
    const float* wproj = (const float*)d_in[8];
    const float* bproj = (const float*)d_in[9];
    const float* g2    = (const float*)d_in[10];
    const float* be2   = (const float*)d_in[11];
    const float* w1f   = (const float*)d_in[12];
    const float* b1f   = (const float*)d_in[13];
    const float* dwk   = (const float*)d_in[14];
    const float* dwb   = (const float*)d_in[15];
    const float* w2f   = (const float*)d_in[16];
    const float* b2f   = (const float*)d_in[17];
    float* out = (float*)d_out;

    float *xn, *qb, *kvb, *awb, *x1, *h1, *hb;
    cudaGetSymbolAddress((void**)&xn,  g_xn);
    cudaGetSymbolAddress((void**)&qb,  g_q);
    cudaGetSymbolAddress((void**)&kvb, g_kv);
    cudaGetSymbolAddress((void**)&awb, g_aw);
    cudaGetSymbolAddress((void**)&x1,  g_x1);
    cudaGetSymbolAddress((void**)&h1,  g_h1);
    cudaGetSymbolAddress((void**)&hb,  g_hb);

    // 1) LN1
    ln_kernel<<<16384, 256>>>(x, g1, be1, xn);
    // 2) q / kv projections (token layout)
    bgemm_kernel<0><<<dim3(2, 1024), 256>>>(xn, wq,  bq,  nullptr, qb,  192, 192);
    bgemm_kernel<0><<<dim3(1, 1024), 256>>>(xn, wkv, bkv, nullptr, kvb, 96,  192);
    // 3) windowed attention (token layout in & out)
    attn_kernel<<<2048, 384>>>(qb, kvb, bt, awb);
    // 4) proj + residual(x) -> x1
    bgemm_kernel<2><<<dim3(2, 1024), 256>>>(awb, wproj, bproj, x, x1, 192, 192);
    // 5) LN2 (reuse xn buffer)
    ln_kernel<<<16384, 256>>>(x1, g2, be2, xn);
    // 6) FFN1 + gelu -> h1
    bgemm_kernel<1><<<dim3(8, 1024), 256>>>(xn, w1f, b1f, nullptr, h1, HIDDEN, 192);
    // 7) depthwise conv branch: hb = h1 + gelu(conv5x5(h1) + dwb)
    dwconv_kernel<<<dim3(3, 256, 2), 256>>>(h1, dwk, dwb, hb);
    // 8) FFN2 + residual(x1) -> out
    bgemm_kernel<2><<<dim3(2, 1024), 256>>>(hb, w2f, b2f, x1, out, 192, HIDDEN);
}